// round 3
// baseline (speedup 1.0000x reference)
#include <cuda_runtime.h>
#include <math.h>

#define NN    100000
#define NNP   100096          // padded to multiple of 128
#define NE    1600000
#define INF   128
#define HID   64
#define OUTF  40
#define GRD   8
#define NFT   1024            // features: f = i*16 + branch*8 + k
#define KT    64              // f per tile
#define KTI   (NFT/KT)        // 16 tiles

typedef unsigned long long ull;

// Scratch (no cudaMalloc allowed)
__device__ float g_bufA[(size_t)NNP * HID];
__device__ float g_bufB[(size_t)NNP * HID];
__device__ float g_Bt[2][NFT * HID];   // transposed coeffs: Bt[f*64 + j]

// ---------------- f32x2 helpers ----------------
__device__ __forceinline__ ull pk2(float s) {
    ull d; unsigned u = __float_as_uint(s);
    asm("mov.b64 %0, {%1,%1};" : "=l"(d) : "r"(u));
    return d;
}
__device__ __forceinline__ void fma2(ull& d, ull a, ull b) {
    asm("fma.rn.f32x2 %0, %1, %2, %0;" : "+l"(d) : "l"(a), "l"(b));
}
__device__ __forceinline__ float2 up2(ull v) {
    unsigned lo, hi;
    asm("mov.b64 {%0,%1}, %2;" : "=r"(lo), "=r"(hi) : "l"(v));
    return make_float2(__uint_as_float(lo), __uint_as_float(hi));
}

// ---------------------------------------------------------------------------
// Transpose coeff [2][64][64][8] -> Bt[1024][64], f = i*16 + b*8 + k
// ---------------------------------------------------------------------------
__global__ __launch_bounds__(256) void transpose_coeff(
    const float* __restrict__ c, float* __restrict__ Bt)
{
    int idx = blockIdx.x * 256 + threadIdx.x;   // over 1024*64
    int j = idx & 63;
    int f = idx >> 6;
    int i = f >> 4, b = (f >> 3) & 1, k = f & 7;
    Bt[idx] = c[(((size_t)b * HID + j) * HID + i) * GRD + k];
}

// ---------------------------------------------------------------------------
// h = x @ W_in + b_in   -> bufA.  W staged in SMEM, f32x2 math.
// 16 nodes per CTA, 256 threads: thread = (node ny, j-quad j4)
// ---------------------------------------------------------------------------
__global__ __launch_bounds__(256) void lin_in_kernel(
    const float* __restrict__ x, const float* __restrict__ W,
    const float* __restrict__ b)
{
    __shared__ float xs[16][INF];
    __shared__ float ws[INF * HID];       // 32 KB
    const int n0  = blockIdx.x * 16;
    const int tid = threadIdx.x;

    for (int idx = tid; idx < INF * HID / 4; idx += 256)
        reinterpret_cast<float4*>(ws)[idx] =
            reinterpret_cast<const float4*>(W)[idx];
    for (int idx = tid; idx < 16 * INF; idx += 256) {
        int n = idx >> 7, c = idx & 127;
        xs[n][c] = x[(size_t)(n0 + n) * INF + c];
    }
    __syncthreads();

    const int j4 = (tid & 15) * 4;
    const int ny = tid >> 4;
    const int n  = n0 + ny;

    ull a01 = 0ULL, a23 = 0ULL;
#pragma unroll 8
    for (int i = 0; i < INF; i++) {
        ull xv = pk2(xs[ny][i]);
        const ull* w2 = reinterpret_cast<const ull*>(ws + i * HID + j4);
        fma2(a01, xv, w2[0]);
        fma2(a23, xv, w2[1]);
    }
    float2 v01 = up2(a01), v23 = up2(a23);
    *reinterpret_cast<float4*>(g_bufA + (size_t)n * HID + j4) =
        make_float4(v01.x + b[j4], v01.y + b[j4 + 1],
                    v23.x + b[j4 + 2], v23.y + b[j4 + 3]);
}

// ---------------------------------------------------------------------------
__global__ __launch_bounds__(256) void zeroB_kernel()
{
    size_t t = (size_t)blockIdx.x * 256 + threadIdx.x;   // float4 index
    reinterpret_cast<float4*>(g_bufB)[t] = make_float4(0.f, 0.f, 0.f, 0.f);
}

// ---------------------------------------------------------------------------
// spmm: out[row[e]] += w[e] * in[col[e]]   (in/out [NNP,64])
// ONE thread per edge: minimal instruction issue; gather stays L2-resident.
// ---------------------------------------------------------------------------
__global__ __launch_bounds__(256) void spmm_kernel(
    const int* __restrict__ erow, const int* __restrict__ ecol,
    const float* __restrict__ ew,
    const float* __restrict__ xin, float* __restrict__ xout)
{
    int e = blockIdx.x * 256 + threadIdx.x;

    int   c  = ecol[e];
    int   r  = erow[e];
    float wv = ew[e];

    const float4* src = reinterpret_cast<const float4*>(xin + (size_t)c * HID);
    float*        dst = xout + (size_t)r * HID;

#pragma unroll
    for (int q = 0; q < 16; q += 4) {
        float4 v0 = __ldg(src + q + 0);
        float4 v1 = __ldg(src + q + 1);
        float4 v2 = __ldg(src + q + 2);
        float4 v3 = __ldg(src + q + 3);
        asm volatile("red.global.add.v4.f32 [%0], {%1,%2,%3,%4};"
                     :: "l"(dst + (q + 0) * 4), "f"(v0.x * wv), "f"(v0.y * wv),
                        "f"(v0.z * wv), "f"(v0.w * wv) : "memory");
        asm volatile("red.global.add.v4.f32 [%0], {%1,%2,%3,%4};"
                     :: "l"(dst + (q + 1) * 4), "f"(v1.x * wv), "f"(v1.y * wv),
                        "f"(v1.z * wv), "f"(v1.w * wv) : "memory");
        asm volatile("red.global.add.v4.f32 [%0], {%1,%2,%3,%4};"
                     :: "l"(dst + (q + 2) * 4), "f"(v2.x * wv), "f"(v2.y * wv),
                        "f"(v2.z * wv), "f"(v2.w * wv) : "memory");
        asm volatile("red.global.add.v4.f32 [%0], {%1,%2,%3,%4};"
                     :: "l"(dst + (q + 3) * 4), "f"(v3.x * wv), "f"(v3.y * wv),
                        "f"(v3.z * wv), "f"(v3.w * wv) : "memory");
    }
}

// ---------------------------------------------------------------------------
// Fourier KAN as SMEM-tiled GEMM with f32x2 packed math.
// CTA: 128 nodes x 64 j. 128 threads, thread tile = 8 nodes (4 pairs) x 8 j.
// ---------------------------------------------------------------------------
__global__ __launch_bounds__(128) void kan_kernel(
    const float* __restrict__ xin, const float* __restrict__ Bt,
    float* __restrict__ xout)
{
    extern __shared__ float sm[];
    float* sx = sm;                       // 64*129
    float* ft = sx + HID * 129;           // 64*128
    float* ct = ft + KT * 128;            // 64*64

    const int tid = threadIdx.x;
    const int n0  = blockIdx.x * 128;
    const int ng  = tid & 15;             // node-pair group
    const int jg  = tid >> 4;             // j group (0..7)

#pragma unroll
    for (int r = 0; r < 64; r++) {
        int idx = r * 128 + tid;
        int i = idx & 63;
        int n = idx >> 6;
        sx[i * 129 + n] = xin[(size_t)(n0 + n) * HID + i];
    }
    __syncthreads();

    ull acc[8][4];
#pragma unroll
    for (int jj = 0; jj < 8; jj++)
#pragma unroll
        for (int p = 0; p < 4; p++) acc[jj][p] = 0ULL;

    for (int kt = 0; kt < KTI; kt++) {
#pragma unroll
        for (int r = 0; r < 4; r++) {
            int idx = tid + 128 * r;
            int n  = idx & 127;
            int ii = idx >> 7;
            float xv = sx[(kt * 4 + ii) * 129 + n];
            float s1, c1;
            sincosf(xv, &s1, &c1);
            float* fcp = ft + (ii * 16) * 128 + n;
            float* fsp = fcp + 8 * 128;
            float twoc = 2.f * c1;
            float cp = 1.f, spv = 0.f, ck = c1, sk = s1;
            fcp[0] = c1; fsp[0] = s1;
#pragma unroll
            for (int k = 1; k < 8; k++) {
                float cn = twoc * ck - cp;
                float sn = twoc * sk - spv;
                cp = ck; spv = sk; ck = cn; sk = sn;
                fcp[k * 128] = ck; fsp[k * 128] = sk;
            }
        }
        {
            const float4* src = reinterpret_cast<const float4*>(Bt + kt * (KT * HID));
            float4* dst = reinterpret_cast<float4*>(ct);
#pragma unroll
            for (int r = 0; r < 8; r++) dst[tid + 128 * r] = src[tid + 128 * r];
        }
        __syncthreads();

#pragma unroll 4
        for (int f = 0; f < KT; f++) {
            const float* ftf = ft + f * 128;
            ull x0 = *reinterpret_cast<const ull*>(ftf + (ng     ) * 2);
            ull x1 = *reinterpret_cast<const ull*>(ftf + (ng + 16) * 2);
            ull x2 = *reinterpret_cast<const ull*>(ftf + (ng + 32) * 2);
            ull x3 = *reinterpret_cast<const ull*>(ftf + (ng + 48) * 2);
            const float* ctf = ct + f * HID + jg * 8;
            float4 cA = *reinterpret_cast<const float4*>(ctf);
            float4 cB = *reinterpret_cast<const float4*>(ctf + 4);
            ull c0 = pk2(cA.x), c1 = pk2(cA.y), c2 = pk2(cA.z), c3 = pk2(cA.w);
            ull c4 = pk2(cB.x), c5 = pk2(cB.y), c6 = pk2(cB.z), c7 = pk2(cB.w);
            fma2(acc[0][0], c0, x0); fma2(acc[0][1], c0, x1); fma2(acc[0][2], c0, x2); fma2(acc[0][3], c0, x3);
            fma2(acc[1][0], c1, x0); fma2(acc[1][1], c1, x1); fma2(acc[1][2], c1, x2); fma2(acc[1][3], c1, x3);
            fma2(acc[2][0], c2, x0); fma2(acc[2][1], c2, x1); fma2(acc[2][2], c2, x2); fma2(acc[2][3], c2, x3);
            fma2(acc[3][0], c3, x0); fma2(acc[3][1], c3, x1); fma2(acc[3][2], c3, x2); fma2(acc[3][3], c3, x3);
            fma2(acc[4][0], c4, x0); fma2(acc[4][1], c4, x1); fma2(acc[4][2], c4, x2); fma2(acc[4][3], c4, x3);
            fma2(acc[5][0], c5, x0); fma2(acc[5][1], c5, x1); fma2(acc[5][2], c5, x2); fma2(acc[5][3], c5, x3);
            fma2(acc[6][0], c6, x0); fma2(acc[6][1], c6, x1); fma2(acc[6][2], c6, x2); fma2(acc[6][3], c6, x3);
            fma2(acc[7][0], c7, x0); fma2(acc[7][1], c7, x1); fma2(acc[7][2], c7, x2); fma2(acc[7][3], c7, x3);
        }
        __syncthreads();
    }

#pragma unroll
    for (int p = 0; p < 4; p++) {
        int node = n0 + (ng + p * 16) * 2;
        float r0[8], r1[8];
#pragma unroll
        for (int jj = 0; jj < 8; jj++) {
            float2 v = up2(acc[jj][p]);
            r0[jj] = v.x; r1[jj] = v.y;
        }
        float4* d0 = reinterpret_cast<float4*>(xout + (size_t)node * HID + jg * 8);
        d0[0] = make_float4(r0[0], r0[1], r0[2], r0[3]);
        d0[1] = make_float4(r0[4], r0[5], r0[6], r0[7]);
        float4* d1 = reinterpret_cast<float4*>(xout + (size_t)(node + 1) * HID + jg * 8);
        d1[0] = make_float4(r1[0], r1[1], r1[2], r1[3]);
        d1[1] = make_float4(r1[4], r1[5], r1[6], r1[7]);
    }
}

// ---------------------------------------------------------------------------
// out = log_softmax(h @ W_out). Warp per node, 8 nodes/CTA, all-SMEM inner loop.
// ---------------------------------------------------------------------------
__global__ __launch_bounds__(256) void out_kernel(
    const float* __restrict__ Wout, float* __restrict__ out)
{
    __shared__ float wsh[HID * OUTF];     // 10 KB
    __shared__ float hsh[8][HID];
    const int tid  = threadIdx.x;
    const int nloc = tid >> 5;
    const int n    = blockIdx.x * 8 + nloc;
    const int lane = tid & 31;

    for (int idx = tid; idx < HID * OUTF; idx += 256) wsh[idx] = Wout[idx];
    for (int idx = tid; idx < 8 * HID; idx += 256) {
        int nl = idx >> 6, i = idx & 63;
        hsh[nl][i] = g_bufA[(size_t)(blockIdx.x * 8 + nl) * HID + i];
    }
    __syncthreads();

    float o0 = 0.f, o1 = 0.f;
#pragma unroll 8
    for (int i = 0; i < HID; i++) {
        float hv = hsh[nloc][i];
        o0 += hv * wsh[i * OUTF + lane];
        if (lane < 8) o1 += hv * wsh[i * OUTF + 32 + lane];
    }

    float m = (lane < 8) ? fmaxf(o0, o1) : o0;
#pragma unroll
    for (int off = 16; off; off >>= 1)
        m = fmaxf(m, __shfl_xor_sync(0xFFFFFFFFu, m, off));

    float e = expf(o0 - m) + ((lane < 8) ? expf(o1 - m) : 0.f);
#pragma unroll
    for (int off = 16; off; off >>= 1)
        e += __shfl_xor_sync(0xFFFFFFFFu, e, off);

    float ls = m + logf(e);
    out[(size_t)n * OUTF + lane] = o0 - ls;
    if (lane < 8) out[(size_t)n * OUTF + 32 + lane] = o1 - ls;
}

// ---------------------------------------------------------------------------
extern "C" void kernel_launch(void* const* d_in, const int* in_sizes, int n_in,
                              void* d_out, int out_size)
{
    const float* x     = (const float*)d_in[0];
    const int*   erow  = (const int*)  d_in[1];
    const int*   ecol  = (const int*)  d_in[2];
    const float* ew    = (const float*)d_in[3];
    const float* W_in  = (const float*)d_in[4];
    const float* b_in  = (const float*)d_in[5];
    const float* c1    = (const float*)d_in[6];
    const float* c2    = (const float*)d_in[7];
    const float* W_out = (const float*)d_in[8];
    float* out = (float*)d_out;

    float *bufA = nullptr, *bufB = nullptr, *Bt = nullptr;
    cudaGetSymbolAddress((void**)&bufA, g_bufA);
    cudaGetSymbolAddress((void**)&bufB, g_bufB);
    cudaGetSymbolAddress((void**)&Bt,   g_Bt);

    const int KAN_SMEM = (HID * 129 + KT * 128 + KT * HID) * (int)sizeof(float);
    cudaFuncSetAttribute(kan_kernel,
                         cudaFuncAttributeMaxDynamicSharedMemorySize, KAN_SMEM);

    const int zeroBlocks = (NNP * HID / 4) / 256;
    const int spmmBlocks = NE / 256;            // 6250, one thread per edge
    const int kanBlocks  = NNP / 128;

    transpose_coeff<<<256, 256>>>(c1, Bt);
    transpose_coeff<<<256, 256>>>(c2, Bt + NFT * HID);
    lin_in_kernel<<<NN / 16, 256>>>(x, W_in, b_in);
    zeroB_kernel<<<zeroBlocks, 256>>>();
    spmm_kernel<<<spmmBlocks, 256>>>(erow, ecol, ew, bufA, bufB);
    kan_kernel<<<kanBlocks, 128, KAN_SMEM>>>(bufB, Bt, bufA);
    zeroB_kernel<<<zeroBlocks, 256>>>();
    spmm_kernel<<<spmmBlocks, 256>>>(erow, ecol, ew, bufA, bufB);
    kan_kernel<<<kanBlocks, 128, KAN_SMEM>>>(bufB, Bt + NFT * HID, bufA);
    out_kernel<<<NN / 8, 256>>>(W_out, out);
}

// round 4
// speedup vs baseline: 1.1224x; 1.1224x over previous
#include <cuda_runtime.h>
#include <math.h>

#define NN    100000
#define NNP   100096          // padded to multiple of 128
#define NE    1600000
#define INF   128
#define HID   64
#define OUTF  40
#define GRD   8
#define NFT   1024            // features: f = i*16 + branch*8 + k
#define KT    64              // f per tile
#define KTI   (NFT/KT)        // 16 tiles

typedef unsigned long long ull;

// Scratch (no cudaMalloc allowed; __device__ globals are zero-initialized)
__device__ float g_bufA[(size_t)NNP * HID];
__device__ float g_bufB[(size_t)NNP * HID];
__device__ float g_Bt[2][NFT * HID];   // transposed coeffs: Bt[f*64 + j]
__device__ int   g_rowstart[NN + 1];
__device__ int   g_cnt[NN];
__device__ int   g_cur[NN];
__device__ ull   g_edges[NE];          // packed (w<<32 | col), CSR-ordered

// ---------------- f32x2 helpers ----------------
__device__ __forceinline__ ull pk2(float s) {
    ull d; unsigned u = __float_as_uint(s);
    asm("mov.b64 %0, {%1,%1};" : "=l"(d) : "r"(u));
    return d;
}
__device__ __forceinline__ void fma2(ull& d, ull a, ull b) {
    asm("fma.rn.f32x2 %0, %1, %2, %0;" : "+l"(d) : "l"(a), "l"(b));
}
__device__ __forceinline__ float2 up2(ull v) {
    unsigned lo, hi;
    asm("mov.b64 {%0,%1}, %2;" : "=r"(lo), "=r"(hi) : "l"(v));
    return make_float2(__uint_as_float(lo), __uint_as_float(hi));
}

// ---------------------------------------------------------------------------
// CSR build: zero counts -> histogram -> scan (+cursor init) -> scatter
// ---------------------------------------------------------------------------
__global__ __launch_bounds__(256) void zero_cnt_kernel()
{
    int i = blockIdx.x * 256 + threadIdx.x;
    if (i < NN) g_cnt[i] = 0;
}

__global__ __launch_bounds__(256) void hist_kernel(const int* __restrict__ erow)
{
    int e = blockIdx.x * 256 + threadIdx.x;
    atomicAdd(&g_cnt[erow[e]], 1);
}

__global__ __launch_bounds__(1024) void scan_kernel()
{
    __shared__ int sh[1024];
    const int tid = threadIdx.x;
    const int CH  = (NN + 1023) / 1024;        // 98
    int lo = min(tid * CH, NN);
    int hi = min(lo + CH, NN);

    int s = 0;
    for (int i = lo; i < hi; i++) s += g_cnt[i];
    sh[tid] = s;
    __syncthreads();
    for (int off = 1; off < 1024; off <<= 1) {
        int v = (tid >= off) ? sh[tid - off] : 0;
        __syncthreads();
        if (tid >= off) sh[tid] += v;
        __syncthreads();
    }
    int run = sh[tid] - s;                     // exclusive prefix
    for (int i = lo; i < hi; i++) {
        g_rowstart[i] = run;
        g_cur[i]      = run;
        run += g_cnt[i];
    }
    if (tid == 1023) g_rowstart[NN] = run;     // == NE
}

__global__ __launch_bounds__(256) void scatter_kernel(
    const int* __restrict__ erow, const int* __restrict__ ecol,
    const float* __restrict__ ew)
{
    int e = blockIdx.x * 256 + threadIdx.x;
    int r = erow[e];
    unsigned c = (unsigned)ecol[e];
    unsigned w = __float_as_uint(ew[e]);
    int pos = atomicAdd(&g_cur[r], 1);
    g_edges[pos] = ((ull)w << 32) | (ull)c;
}

// ---------------------------------------------------------------------------
// CSR spmm: out[n] = sum_e w_e * in[col_e].  Warp per node, lane = 2 features.
// No atomics; gather coalesced 256B per edge; store coalesced.
// ---------------------------------------------------------------------------
__global__ __launch_bounds__(256) void spmm_csr_kernel(
    const float* __restrict__ xin, float* __restrict__ xout)
{
    const int node = blockIdx.x * 8 + (threadIdx.x >> 5);
    const int lane = threadIdx.x & 31;

    int s = g_rowstart[node];
    int e = g_rowstart[node + 1];

    ull acc = 0ULL;
    int i = s;
    for (; i + 4 <= e; i += 4) {
        ull p0 = __ldg(g_edges + i + 0);
        ull p1 = __ldg(g_edges + i + 1);
        ull p2 = __ldg(g_edges + i + 2);
        ull p3 = __ldg(g_edges + i + 3);
        int c0 = (int)(unsigned)p0, c1 = (int)(unsigned)p1;
        int c2 = (int)(unsigned)p2, c3 = (int)(unsigned)p3;
        ull v0 = *reinterpret_cast<const ull*>(xin + (size_t)c0 * HID + lane * 2);
        ull v1 = *reinterpret_cast<const ull*>(xin + (size_t)c1 * HID + lane * 2);
        ull v2 = *reinterpret_cast<const ull*>(xin + (size_t)c2 * HID + lane * 2);
        ull v3 = *reinterpret_cast<const ull*>(xin + (size_t)c3 * HID + lane * 2);
        fma2(acc, pk2(__uint_as_float((unsigned)(p0 >> 32))), v0);
        fma2(acc, pk2(__uint_as_float((unsigned)(p1 >> 32))), v1);
        fma2(acc, pk2(__uint_as_float((unsigned)(p2 >> 32))), v2);
        fma2(acc, pk2(__uint_as_float((unsigned)(p3 >> 32))), v3);
    }
    for (; i < e; i++) {
        ull p = __ldg(g_edges + i);
        int c = (int)(unsigned)p;
        ull v = *reinterpret_cast<const ull*>(xin + (size_t)c * HID + lane * 2);
        fma2(acc, pk2(__uint_as_float((unsigned)(p >> 32))), v);
    }
    *reinterpret_cast<ull*>(xout + (size_t)node * HID + lane * 2) = acc;
}

// ---------------------------------------------------------------------------
// Transpose coeff [2][64][64][8] -> Bt[1024][64], f = i*16 + b*8 + k
// ---------------------------------------------------------------------------
__global__ __launch_bounds__(256) void transpose_coeff(
    const float* __restrict__ c, float* __restrict__ Bt)
{
    int idx = blockIdx.x * 256 + threadIdx.x;   // over 1024*64
    int j = idx & 63;
    int f = idx >> 6;
    int i = f >> 4, b = (f >> 3) & 1, k = f & 7;
    Bt[idx] = c[(((size_t)b * HID + j) * HID + i) * GRD + k];
}

// ---------------------------------------------------------------------------
// h = x @ W_in + b_in   -> bufA.  W staged in SMEM, f32x2 math.
// ---------------------------------------------------------------------------
__global__ __launch_bounds__(256) void lin_in_kernel(
    const float* __restrict__ x, const float* __restrict__ W,
    const float* __restrict__ b)
{
    __shared__ float xs[16][INF];
    __shared__ float ws[INF * HID];       // 32 KB
    const int n0  = blockIdx.x * 16;
    const int tid = threadIdx.x;

    for (int idx = tid; idx < INF * HID / 4; idx += 256)
        reinterpret_cast<float4*>(ws)[idx] =
            reinterpret_cast<const float4*>(W)[idx];
    for (int idx = tid; idx < 16 * INF; idx += 256) {
        int n = idx >> 7, c = idx & 127;
        xs[n][c] = x[(size_t)(n0 + n) * INF + c];
    }
    __syncthreads();

    const int j4 = (tid & 15) * 4;
    const int ny = tid >> 4;
    const int n  = n0 + ny;

    ull a01 = 0ULL, a23 = 0ULL;
#pragma unroll 8
    for (int i = 0; i < INF; i++) {
        ull xv = pk2(xs[ny][i]);
        const ull* w2 = reinterpret_cast<const ull*>(ws + i * HID + j4);
        fma2(a01, xv, w2[0]);
        fma2(a23, xv, w2[1]);
    }
    float2 v01 = up2(a01), v23 = up2(a23);
    *reinterpret_cast<float4*>(g_bufA + (size_t)n * HID + j4) =
        make_float4(v01.x + b[j4], v01.y + b[j4 + 1],
                    v23.x + b[j4 + 2], v23.y + b[j4 + 3]);
}

// ---------------------------------------------------------------------------
// Fourier KAN as SMEM-tiled GEMM with f32x2 packed math.
// CTA: 128 nodes x 64 j. 128 threads, thread tile = 8 nodes (4 pairs) x 8 j.
// ---------------------------------------------------------------------------
__global__ __launch_bounds__(128) void kan_kernel(
    const float* __restrict__ xin, const float* __restrict__ Bt,
    float* __restrict__ xout)
{
    extern __shared__ float sm[];
    float* sx = sm;                       // 64*129
    float* ft = sx + HID * 129;           // 64*128
    float* ct = ft + KT * 128;            // 64*64

    const int tid = threadIdx.x;
    const int n0  = blockIdx.x * 128;
    const int ng  = tid & 15;             // node-pair group
    const int jg  = tid >> 4;             // j group (0..7)

#pragma unroll
    for (int r = 0; r < 64; r++) {
        int idx = r * 128 + tid;
        int i = idx & 63;
        int n = idx >> 6;
        sx[i * 129 + n] = xin[(size_t)(n0 + n) * HID + i];
    }
    __syncthreads();

    ull acc[8][4];
#pragma unroll
    for (int jj = 0; jj < 8; jj++)
#pragma unroll
        for (int p = 0; p < 4; p++) acc[jj][p] = 0ULL;

    for (int kt = 0; kt < KTI; kt++) {
#pragma unroll
        for (int r = 0; r < 4; r++) {
            int idx = tid + 128 * r;
            int n  = idx & 127;
            int ii = idx >> 7;
            float xv = sx[(kt * 4 + ii) * 129 + n];
            float s1, c1;
            sincosf(xv, &s1, &c1);
            float* fcp = ft + (ii * 16) * 128 + n;
            float* fsp = fcp + 8 * 128;
            float twoc = 2.f * c1;
            float cp = 1.f, spv = 0.f, ck = c1, sk = s1;
            fcp[0] = c1; fsp[0] = s1;
#pragma unroll
            for (int k = 1; k < 8; k++) {
                float cn = twoc * ck - cp;
                float sn = twoc * sk - spv;
                cp = ck; spv = sk; ck = cn; sk = sn;
                fcp[k * 128] = ck; fsp[k * 128] = sk;
            }
        }
        {
            const float4* src = reinterpret_cast<const float4*>(Bt + kt * (KT * HID));
            float4* dst = reinterpret_cast<float4*>(ct);
#pragma unroll
            for (int r = 0; r < 8; r++) dst[tid + 128 * r] = src[tid + 128 * r];
        }
        __syncthreads();

#pragma unroll 4
        for (int f = 0; f < KT; f++) {
            const float* ftf = ft + f * 128;
            ull x0 = *reinterpret_cast<const ull*>(ftf + (ng     ) * 2);
            ull x1 = *reinterpret_cast<const ull*>(ftf + (ng + 16) * 2);
            ull x2 = *reinterpret_cast<const ull*>(ftf + (ng + 32) * 2);
            ull x3 = *reinterpret_cast<const ull*>(ftf + (ng + 48) * 2);
            const float* ctf = ct + f * HID + jg * 8;
            float4 cA = *reinterpret_cast<const float4*>(ctf);
            float4 cB = *reinterpret_cast<const float4*>(ctf + 4);
            ull c0 = pk2(cA.x), c1 = pk2(cA.y), c2 = pk2(cA.z), c3 = pk2(cA.w);
            ull c4 = pk2(cB.x), c5 = pk2(cB.y), c6 = pk2(cB.z), c7 = pk2(cB.w);
            fma2(acc[0][0], c0, x0); fma2(acc[0][1], c0, x1); fma2(acc[0][2], c0, x2); fma2(acc[0][3], c0, x3);
            fma2(acc[1][0], c1, x0); fma2(acc[1][1], c1, x1); fma2(acc[1][2], c1, x2); fma2(acc[1][3], c1, x3);
            fma2(acc[2][0], c2, x0); fma2(acc[2][1], c2, x1); fma2(acc[2][2], c2, x2); fma2(acc[2][3], c2, x3);
            fma2(acc[3][0], c3, x0); fma2(acc[3][1], c3, x1); fma2(acc[3][2], c3, x2); fma2(acc[3][3], c3, x3);
            fma2(acc[4][0], c4, x0); fma2(acc[4][1], c4, x1); fma2(acc[4][2], c4, x2); fma2(acc[4][3], c4, x3);
            fma2(acc[5][0], c5, x0); fma2(acc[5][1], c5, x1); fma2(acc[5][2], c5, x2); fma2(acc[5][3], c5, x3);
            fma2(acc[6][0], c6, x0); fma2(acc[6][1], c6, x1); fma2(acc[6][2], c6, x2); fma2(acc[6][3], c6, x3);
            fma2(acc[7][0], c7, x0); fma2(acc[7][1], c7, x1); fma2(acc[7][2], c7, x2); fma2(acc[7][3], c7, x3);
        }
        __syncthreads();
    }

#pragma unroll
    for (int p = 0; p < 4; p++) {
        int node = n0 + (ng + p * 16) * 2;
        float r0[8], r1[8];
#pragma unroll
        for (int jj = 0; jj < 8; jj++) {
            float2 v = up2(acc[jj][p]);
            r0[jj] = v.x; r1[jj] = v.y;
        }
        float4* d0 = reinterpret_cast<float4*>(xout + (size_t)node * HID + jg * 8);
        d0[0] = make_float4(r0[0], r0[1], r0[2], r0[3]);
        d0[1] = make_float4(r0[4], r0[5], r0[6], r0[7]);
        float4* d1 = reinterpret_cast<float4*>(xout + (size_t)(node + 1) * HID + jg * 8);
        d1[0] = make_float4(r1[0], r1[1], r1[2], r1[3]);
        d1[1] = make_float4(r1[4], r1[5], r1[6], r1[7]);
    }
}

// ---------------------------------------------------------------------------
// out = log_softmax(h @ W_out). Warp per node, 8 nodes/CTA, all-SMEM inner loop.
// ---------------------------------------------------------------------------
__global__ __launch_bounds__(256) void out_kernel(
    const float* __restrict__ Wout, float* __restrict__ out)
{
    __shared__ float wsh[HID * OUTF];     // 10 KB
    __shared__ float hsh[8][HID];
    const int tid  = threadIdx.x;
    const int nloc = tid >> 5;
    const int n    = blockIdx.x * 8 + nloc;
    const int lane = tid & 31;

    for (int idx = tid; idx < HID * OUTF; idx += 256) wsh[idx] = Wout[idx];
    for (int idx = tid; idx < 8 * HID; idx += 256) {
        int nl = idx >> 6, i = idx & 63;
        hsh[nl][i] = g_bufA[(size_t)(blockIdx.x * 8 + nl) * HID + i];
    }
    __syncthreads();

    float o0 = 0.f, o1 = 0.f;
#pragma unroll 8
    for (int i = 0; i < HID; i++) {
        float hv = hsh[nloc][i];
        o0 += hv * wsh[i * OUTF + lane];
        if (lane < 8) o1 += hv * wsh[i * OUTF + 32 + lane];
    }

    float m = (lane < 8) ? fmaxf(o0, o1) : o0;
#pragma unroll
    for (int off = 16; off; off >>= 1)
        m = fmaxf(m, __shfl_xor_sync(0xFFFFFFFFu, m, off));

    float e = expf(o0 - m) + ((lane < 8) ? expf(o1 - m) : 0.f);
#pragma unroll
    for (int off = 16; off; off >>= 1)
        e += __shfl_xor_sync(0xFFFFFFFFu, e, off);

    float ls = m + logf(e);
    out[(size_t)n * OUTF + lane] = o0 - ls;
    if (lane < 8) out[(size_t)n * OUTF + 32 + lane] = o1 - ls;
}

// ---------------------------------------------------------------------------
extern "C" void kernel_launch(void* const* d_in, const int* in_sizes, int n_in,
                              void* d_out, int out_size)
{
    const float* x     = (const float*)d_in[0];
    const int*   erow  = (const int*)  d_in[1];
    const int*   ecol  = (const int*)  d_in[2];
    const float* ew    = (const float*)d_in[3];
    const float* W_in  = (const float*)d_in[4];
    const float* b_in  = (const float*)d_in[5];
    const float* c1    = (const float*)d_in[6];
    const float* c2    = (const float*)d_in[7];
    const float* W_out = (const float*)d_in[8];
    float* out = (float*)d_out;

    float *bufA = nullptr, *bufB = nullptr, *Bt = nullptr;
    cudaGetSymbolAddress((void**)&bufA, g_bufA);
    cudaGetSymbolAddress((void**)&bufB, g_bufB);
    cudaGetSymbolAddress((void**)&Bt,   g_Bt);

    const int KAN_SMEM = (HID * 129 + KT * 128 + KT * HID) * (int)sizeof(float);
    cudaFuncSetAttribute(kan_kernel,
                         cudaFuncAttributeMaxDynamicSharedMemorySize, KAN_SMEM);

    const int kanBlocks = NNP / 128;

    // CSR build (every launch; deterministic, allocation-free)
    zero_cnt_kernel<<<(NN + 255) / 256, 256>>>();
    hist_kernel<<<NE / 256, 256>>>(erow);
    scan_kernel<<<1, 1024>>>();
    scatter_kernel<<<NE / 256, 256>>>(erow, ecol, ew);

    // coeff transpose + lin_in (independent of CSR build)
    transpose_coeff<<<256, 256>>>(c1, Bt);
    transpose_coeff<<<256, 256>>>(c2, Bt + NFT * HID);
    lin_in_kernel<<<NN / 16, 256>>>(x, W_in, b_in);

    // pipeline
    spmm_csr_kernel<<<NN / 8, 256>>>(bufA, bufB);
    kan_kernel<<<kanBlocks, 128, KAN_SMEM>>>(bufB, Bt, bufA);
    spmm_csr_kernel<<<NN / 8, 256>>>(bufA, bufB);
    kan_kernel<<<kanBlocks, 128, KAN_SMEM>>>(bufB, Bt + NFT * HID, bufA);
    out_kernel<<<NN / 8, 256>>>(W_out, out);
}